// round 8
// baseline (speedup 1.0000x reference)
#include <cuda_runtime.h>
#include <cuda_bf16.h>
#include <cstdint>
#include <cstddef>

#define N_NODES 100000
#define N_EDGES 1600000
#define N_GRAPHS 4096
#define HID 512
#define M_PAD 100096            // 782 * 128, multiple of 16
#define NCHUNK ((N_NODES + 1023) / 1024)

// ---------------- scratch (device globals; allocation-free) ----------------
__device__ float g_h[(size_t)N_NODES * HID];          // row-major node features
__device__ float g_t[(size_t)M_PAD * HID];            // A-perm: agg output
__device__ float g_m[(size_t)M_PAD * HID];            // A-perm: MLP hidden
__device__ float g_h7[(size_t)N_NODES * 7];
__device__ float g_pool[(size_t)N_GRAPHS * HID];
__device__ float g_p1[(size_t)N_GRAPHS * 256];
__device__ float g_wt[5 * 512 * 512 + 256 * 512];     // 5 B-perm weights + plain lw1
// CSR scratch
__device__ int g_deg[N_NODES];
__device__ int g_rows[N_NODES + 1];
__device__ int g_cur[N_NODES];
__device__ int g_csr[N_EDGES];
__device__ int g_gstart[N_GRAPHS + 1];
__device__ int g_bsum[NCHUNK];
__device__ int g_boff[NCHUNK];

__device__ __forceinline__ uint32_t f2tf32(float x) {
    uint32_t r;
    asm("cvt.rna.tf32.f32 %0, %1;" : "=r"(r) : "f"(x));
    return r;
}
__device__ __forceinline__ float roundtf(float x) { return __uint_as_float(f2tf32(x)); }

// A-perm index (K=512): 16x8 tiles, 128 words each.
// lane = (m%8)*4 + (k%4), slot = ((m>>3)&1) + ((k>>2)&1)*2
__device__ __forceinline__ size_t pa_idx(int m, int k) {
    return ((size_t)(m >> 4) * 64 + (k >> 3)) * 128
         + (((m & 7) * 4 + (k & 3)) << 2) + ((m >> 3) & 1) + (((k >> 2) & 1) << 1);
}

// ---------------- CSR build ----------------
__global__ void deg_count(const int* __restrict__ dst) {
    int e = blockIdx.x * blockDim.x + threadIdx.x;
    if (e < N_EDGES) atomicAdd(&g_deg[dst[e]], 1);
}

__global__ __launch_bounds__(1024) void scan1() {
    __shared__ int s[1024];
    const int b = blockIdx.x;
    const int tid = threadIdx.x;
    const int i = b * 1024 + tid;
    int v = (i < N_NODES) ? g_deg[i] : 0;
    s[tid] = v;
    __syncthreads();
#pragma unroll
    for (int off = 1; off < 1024; off <<= 1) {
        int t = (tid >= off) ? s[tid - off] : 0;
        __syncthreads();
        s[tid] += t;
        __syncthreads();
    }
    if (i < N_NODES) g_rows[i] = s[tid] - v;
    if (tid == 1023) g_bsum[b] = s[1023];
}

__global__ void scan2() {
    if (threadIdx.x == 0) {
        int c = 0;
        for (int b = 0; b < NCHUNK; b++) { g_boff[b] = c; c += g_bsum[b]; }
        g_rows[N_NODES] = c;
    }
}

__global__ __launch_bounds__(1024) void scan3() {
    const int b = blockIdx.x;
    const int i = b * 1024 + threadIdx.x;
    if (i < N_NODES) {
        int r = g_rows[i] + g_boff[b];
        g_rows[i] = r;
        g_cur[i] = r;
    }
}

__global__ void csr_scatter(const int* __restrict__ src, const int* __restrict__ dst) {
    int e = blockIdx.x * blockDim.x + threadIdx.x;
    if (e >= N_EDGES) return;
    int pos = atomicAdd(&g_cur[dst[e]], 1);
    g_csr[pos] = src[e];
}

__global__ void graph_ranges(const int* __restrict__ batch) {
    int g = blockIdx.x * blockDim.x + threadIdx.x;
    if (g > N_GRAPHS) return;
    if (g == N_GRAPHS) { g_gstart[g] = N_NODES; return; }
    int lo = 0, hi = N_NODES;
    while (lo < hi) {
        int mid = (lo + hi) >> 1;
        if (batch[mid] < g) lo = mid + 1; else hi = mid;
    }
    g_gstart[g] = lo;
}

// ---------------- layer-1 aggregation (7 feats) ----------------
__global__ void csr_agg7(const float* __restrict__ x) {
    int w = (int)(((long long)blockIdx.x * blockDim.x + threadIdx.x) >> 5);
    int lane = threadIdx.x & 31;
    if (w >= N_NODES) return;
    int beg = g_rows[w], end = g_rows[w + 1];
    float a[7];
#pragma unroll
    for (int k = 0; k < 7; k++) a[k] = (lane == 0) ? x[(size_t)w * 7 + k] : 0.f;
    for (int e = beg + lane; e < end; e += 32) {
        int s = g_csr[e];
#pragma unroll
        for (int k = 0; k < 7; k++) a[k] += x[(size_t)s * 7 + k];
    }
#pragma unroll
    for (int off = 16; off; off >>= 1)
#pragma unroll
        for (int k = 0; k < 7; k++) a[k] += __shfl_xor_sync(0xFFFFFFFF, a[k], off);
    if (lane == 0) {
#pragma unroll
        for (int k = 0; k < 7; k++) g_h7[(size_t)w * 7 + k] = a[k];
    }
}

// g_m(perm) = round_tf32(relu(g_h7 @ w1 + b1)) — exact fp32 math
__global__ __launch_bounds__(256) void mlp_in7(const float* __restrict__ w,
                                               const float* __restrict__ bias) {
    __shared__ float sw[7][512];
    __shared__ float sb[512];
    for (int i = threadIdx.x; i < 7 * 512; i += 256) ((float*)sw)[i] = w[i];
    for (int i = threadIdx.x; i < 512; i += 256) sb[i] = bias[i];
    __syncthreads();
    for (int r = blockIdx.x; r < N_NODES; r += gridDim.x) {
        float h[7];
#pragma unroll
        for (int k = 0; k < 7; k++) h[k] = g_h7[(size_t)r * 7 + k];
#pragma unroll
        for (int jj = 0; jj < 2; jj++) {
            int j = threadIdx.x + jj * 256;
            float acc = sb[j];
#pragma unroll
            for (int k = 0; k < 7; k++) acc = fmaf(h[k], sw[k][j], acc);
            g_m[pa_idx(r, j)] = roundtf(fmaxf(acc, 0.f));
        }
    }
}

// ---------------- L2-blocked 512-wide aggregation -> g_t (A-perm) ----------------
__global__ __launch_bounds__(256) void csr_agg512_chunk() {
    int w = (int)(((long long)blockIdx.x * blockDim.x + threadIdx.x) >> 5);
    int lane = threadIdx.x & 31;
    if (w >= N_NODES) return;
    const int off = blockIdx.y * 128 + lane * 4;  // kbase, %4==0
    const int beg = g_rows[w], end = g_rows[w + 1];
    const float* base = g_h + off;

    float4 acc = *(const float4*)(base + (size_t)w * HID);

    int e = beg;
    for (; e + 4 <= end; e += 4) {
        int s0 = g_csr[e], s1 = g_csr[e + 1], s2 = g_csr[e + 2], s3 = g_csr[e + 3];
        float4 v0 = *(const float4*)(base + (size_t)s0 * HID);
        float4 v1 = *(const float4*)(base + (size_t)s1 * HID);
        float4 v2 = *(const float4*)(base + (size_t)s2 * HID);
        float4 v3 = *(const float4*)(base + (size_t)s3 * HID);
        acc.x += v0.x + v1.x + v2.x + v3.x;
        acc.y += v0.y + v1.y + v2.y + v3.y;
        acc.z += v0.z + v1.z + v2.z + v3.z;
        acc.w += v0.w + v1.w + v2.w + v3.w;
    }
    for (; e < end; e++) {
        int s0 = g_csr[e];
        float4 v = *(const float4*)(base + (size_t)s0 * HID);
        acc.x += v.x; acc.y += v.y; acc.z += v.z; acc.w += v.w;
    }

    // permuted store: tile(kt=off>>3), lane=(w%8)*4+c3, slot=((w>>3)&1)+((off>>2)&1)*2
    size_t tb = ((size_t)(w >> 4) * 64 + (off >> 3)) * 128
              + ((w & 7) << 4) + ((w >> 3) & 1) + (((off >> 2) & 1) << 1);
    g_t[tb + 0]  = roundtf(acc.x);
    g_t[tb + 4]  = roundtf(acc.y);
    g_t[tb + 8]  = roundtf(acc.z);
    g_t[tb + 12] = roundtf(acc.w);
}

// weights [K,N] -> B-perm [nt,kt] tiles (8x8, 64 words), tf32-rounded
__global__ void w_to_bperm(const float* __restrict__ in, float* __restrict__ outp,
                           int K, int N) {
    int idx = blockIdx.x * blockDim.x + threadIdx.x;
    if (idx >= K * N) return;
    int k = idx / N, n = idx % N;
    size_t a = ((size_t)(n >> 3) * (K >> 3) + (k >> 3)) * 64
             + (((n & 7) * 4 + (k & 3)) << 1) + ((k >> 2) & 1);
    outp[a] = roundtf(in[idx]);
}

// transpose [K,N] -> [N,K], tf32-round (plain, for head lw1)
__global__ void transposeKN(const float* __restrict__ in, float* __restrict__ outp,
                            int K, int N) {
    __shared__ float t[32][33];
    int n0 = blockIdx.x * 32, k0 = blockIdx.y * 32;
    int tx = threadIdx.x, ty = threadIdx.y;
#pragma unroll
    for (int i = 0; i < 4; i++)
        t[ty + i * 8][tx] = in[(size_t)(k0 + ty + i * 8) * N + n0 + tx];
    __syncthreads();
#pragma unroll
    for (int i = 0; i < 4; i++)
        outp[(size_t)(n0 + ty + i * 8) * K + k0 + tx] = roundtf(t[tx][ty + i * 8]);
}

// ---------------- shared mma helpers ----------------
__device__ __forceinline__ void cp16(uint32_t dst, const void* src, int sz) {
    asm volatile("cp.async.cg.shared.global [%0], [%1], 16, %2;"
                 :: "r"(dst), "l"(src), "r"(sz));
}

__device__ __forceinline__ void mma1688u(float* d, const uint32_t* a, const uint32_t* b) {
    asm volatile(
        "mma.sync.aligned.m16n8k8.row.col.f32.tf32.tf32.f32 "
        "{%0,%1,%2,%3},{%4,%5,%6,%7},{%8,%9},{%0,%1,%2,%3};\n"
        : "+f"(d[0]), "+f"(d[1]), "+f"(d[2]), "+f"(d[3])
        : "r"(a[0]), "r"(a[1]), "r"(a[2]), "r"(a[3]), "r"(b[0]), "r"(b[1]));
}

__device__ __forceinline__ void mma1688(float* d, const float* a, const float* b) {
    asm volatile(
        "mma.sync.aligned.m16n8k8.row.col.f32.tf32.tf32.f32 "
        "{%0,%1,%2,%3},{%4,%5,%6,%7},{%8,%9},{%0,%1,%2,%3};\n"
        : "+f"(d[0]), "+f"(d[1]), "+f"(d[2]), "+f"(d[3])
        : "r"(__float_as_uint(a[0])), "r"(__float_as_uint(a[1])),
          "r"(__float_as_uint(a[2])), "r"(__float_as_uint(a[3])),
          "r"(__float_as_uint(b[0])), "r"(__float_as_uint(b[1])));
}

#define STG_WORDS 8192
#define STG_BYTES (STG_WORDS * 4)
#define GSM_BYTES (3 * STG_BYTES)  // 96 KB

// ---------------- perm-layout TF32 GEMM (A-perm x B-perm) ----------------
// A: [M_PAD/16 x K/8] tiles of 128 words. B: [N/8 x K/8] tiles of 64 words.
// PERM_OUT: C written A-perm (padded, unguarded) with round; else row-major guarded.
template <bool PERM_OUT>
__global__ __launch_bounds__(256) void gemm_pp(
    int M, int ktn /* K/8 */, int ldc,
    const float* __restrict__ A, const float* __restrict__ Bp,
    const float* __restrict__ bias,
    float* __restrict__ C) {
    extern __shared__ __align__(128) char smc[];
    uint32_t smem_u32;
    asm("{ .reg .u64 t; cvta.to.shared.u64 t, %1; cvt.u32.u64 %0, t; }"
        : "=r"(smem_u32) : "l"(smc));

    const int tid = threadIdx.x;
    const int lane = tid & 31;
    const int warp = tid >> 5;
    const int wy = warp & 1;
    const int wx = warp >> 1;
    const int m0 = blockIdx.y * 128;
    const int n0 = blockIdx.x * 128;
    const int mt0 = m0 >> 4;
    const int nt0 = n0 >> 3;

    const int nks = ktn >> 2;  // K/32 chunks

    auto issue = [&](int ks) {
        uint32_t sa = smem_u32 + (uint32_t)(ks % 3) * STG_BYTES;
        uint32_t sb = sa + 16384;
        const int k4 = ks * 4;
#pragma unroll
        for (int q = 0; q < 4; q++) {
            int idx = q * 256 + tid;
            int tile = idx >> 5, li = idx & 31;
            const float* src = A + ((size_t)(mt0 + (tile >> 2)) * ktn + k4 + (tile & 3)) * 128 + li * 4;
            cp16(sa + (uint32_t)(tile * 512 + li * 16), src, 16);
        }
#pragma unroll
        for (int q = 0; q < 4; q++) {
            int idx = q * 256 + tid;
            int tile = idx >> 4, hi = idx & 15;
            const float* src = Bp + ((size_t)(nt0 + (tile >> 2)) * ktn + k4 + (tile & 3)) * 64 + hi * 4;
            cp16(sb + (uint32_t)(tile * 256 + hi * 16), src, 16);
        }
        asm volatile("cp.async.commit_group;");
    };

    issue(0);
    issue(1);

    float acc[4][4][4];
#pragma unroll
    for (int i = 0; i < 4; i++)
#pragma unroll
        for (int j = 0; j < 4; j++)
#pragma unroll
            for (int r = 0; r < 4; r++) acc[i][j][r] = 0.f;

    for (int ks = 0; ks < nks; ks++) {
        if (ks + 2 < nks) issue(ks + 2);
        else asm volatile("cp.async.commit_group;");
        asm volatile("cp.async.wait_group %0;" :: "n"(2));
        __syncthreads();

        const char* sA = smc + (ks % 3) * STG_BYTES;
        const char* sB = sA + 16384;
#pragma unroll
        for (int kk = 0; kk < 4; kk++) {
            uint4 af[4];
            uint2 bf[4];
#pragma unroll
            for (int i = 0; i < 4; i++)
                af[i] = *(const uint4*)(sA + ((((wy * 4 + i) * 4 + kk) << 9) + (lane << 4)));
#pragma unroll
            for (int j = 0; j < 4; j++)
                bf[j] = *(const uint2*)(sB + ((((wx * 4 + j) * 4 + kk) << 8) + (lane << 3)));
#pragma unroll
            for (int i = 0; i < 4; i++)
#pragma unroll
                for (int j = 0; j < 4; j++)
                    mma1688u(acc[i][j], (const uint32_t*)&af[i], (const uint32_t*)&bf[j]);
        }
        __syncthreads();
    }

    const int crow = lane >> 2;      // 0..7
    const int ccol = (lane & 3) << 1;
#pragma unroll
    for (int i = 0; i < 4; i++) {
        int r0 = m0 + wy * 64 + i * 16 + crow;  // r0%16 = crow < 8
#pragma unroll
        for (int j = 0; j < 4; j++) {
            int c = n0 + wx * 32 + j * 8 + ccol;
            float b0 = bias[c], b1 = bias[c + 1];
            float v00 = fmaxf(acc[i][j][0] + b0, 0.f);
            float v01 = fmaxf(acc[i][j][1] + b1, 0.f);
            float v10 = fmaxf(acc[i][j][2] + b0, 0.f);
            float v11 = fmaxf(acc[i][j][3] + b1, 0.f);
            if (PERM_OUT) {
                // C is A-perm (padded), round to tf32
                size_t base = ((size_t)(r0 >> 4) * 64 + (c >> 3)) * 128
                            + ((crow * 4 + (c & 3)) << 2) + (((c >> 2) & 1) << 1);
                C[base + 0] = roundtf(v00);
                C[base + 4] = roundtf(v01);
                C[base + 1] = roundtf(v10);
                C[base + 5] = roundtf(v11);
            } else {
                int r1 = r0 + 8;
                if (r0 < M) { float2 v = {v00, v01}; *(float2*)&C[(size_t)r0 * ldc + c] = v; }
                if (r1 < M) { float2 v = {v10, v11}; *(float2*)&C[(size_t)r1 * ldc + c] = v; }
            }
        }
    }
}

// ---------------- plain-layout GEMM (head only) ----------------
template <bool ROUND_OUT>
__global__ __launch_bounds__(256) void gemm_ca(
    int M, int K, int ldc,
    const float* __restrict__ A, const float* __restrict__ Bt,
    const float* __restrict__ bias,
    float* __restrict__ C) {
    extern __shared__ __align__(128) float smf[];
    uint32_t smem_u32;
    asm("{ .reg .u64 t; cvta.to.shared.u64 t, %1; cvt.u32.u64 %0, t; }"
        : "=r"(smem_u32) : "l"(smf));

    const int tid = threadIdx.x;
    const int lane = tid & 31;
    const int warp = tid >> 5;
    const int wy = warp & 1;
    const int wx = warp >> 1;
    const int m0 = blockIdx.y * 128;
    const int n0 = blockIdx.x * 128;

    const int cprow = tid >> 3;
    const int cpc4 = tid & 7;
    const int cpswz = (cpc4 ^ (cprow & 7)) << 2;

    const int nks = K >> 5;

    auto issue = [&](int ks) {
        uint32_t sa = smem_u32 + (uint32_t)(ks % 3) * STG_BYTES;
        uint32_t sb = sa + 16384;
#pragma unroll
        for (int q = 0; q < 4; q++) {
            int row = cprow + q * 32;
            int grow = m0 + row;
            const float* src = A + (size_t)(grow < M ? grow : 0) * K + ks * 32 + cpc4 * 4;
            cp16(sa + (uint32_t)(row * 32 + cpswz) * 4, src, grow < M ? 16 : 0);
        }
#pragma unroll
        for (int q = 0; q < 4; q++) {
            int row = cprow + q * 32;
            const float* src = Bt + (size_t)(n0 + row) * K + ks * 32 + cpc4 * 4;
            cp16(sb + (uint32_t)(row * 32 + cpswz) * 4, src, 16);
        }
        asm volatile("cp.async.commit_group;");
    };

    issue(0);
    issue(1);

    float acc[4][4][4];
#pragma unroll
    for (int i = 0; i < 4; i++)
#pragma unroll
        for (int j = 0; j < 4; j++)
#pragma unroll
            for (int r = 0; r < 4; r++) acc[i][j][r] = 0.f;

    const int r8 = lane >> 2;
    const int c3 = lane & 3;

    for (int ks = 0; ks < nks; ks++) {
        if (ks + 2 < nks) issue(ks + 2);
        else asm volatile("cp.async.commit_group;");
        asm volatile("cp.async.wait_group %0;" :: "n"(2));
        __syncthreads();

        const float* sA = smf + (ks % 3) * STG_WORDS;
        const float* sB = sA + 4096;
#pragma unroll
        for (int kk = 0; kk < 4; kk++) {
            float a[4][4];
#pragma unroll
            for (int i = 0; i < 4; i++) {
                int row = wy * 64 + i * 16 + r8;
                int base = row * 32;
                int ch0 = ((kk * 2) ^ r8) * 4 + c3;
                int ch1 = ((kk * 2 + 1) ^ r8) * 4 + c3;
                a[i][0] = sA[base + ch0];
                a[i][1] = sA[base + 256 + ch0];
                a[i][2] = sA[base + ch1];
                a[i][3] = sA[base + 256 + ch1];
            }
            float b[4][2];
#pragma unroll
            for (int j = 0; j < 4; j++) {
                int n = wx * 32 + j * 8 + r8;
                int base = n * 32;
                b[j][0] = sB[base + ((kk * 2) ^ r8) * 4 + c3];
                b[j][1] = sB[base + ((kk * 2 + 1) ^ r8) * 4 + c3];
            }
#pragma unroll
            for (int i = 0; i < 4; i++)
#pragma unroll
                for (int j = 0; j < 4; j++) mma1688(acc[i][j], a[i], b[j]);
        }
        __syncthreads();
    }

    const int crow = r8;
    const int ccol = c3 << 1;
#pragma unroll
    for (int i = 0; i < 4; i++) {
        int r0 = m0 + wy * 64 + i * 16 + crow;
        int r1 = r0 + 8;
#pragma unroll
        for (int j = 0; j < 4; j++) {
            int c = n0 + wx * 32 + j * 8 + ccol;
            float b0 = bias[c], b1 = bias[c + 1];
            float2 v0, v1;
            v0.x = fmaxf(acc[i][j][0] + b0, 0.f);
            v0.y = fmaxf(acc[i][j][1] + b1, 0.f);
            v1.x = fmaxf(acc[i][j][2] + b0, 0.f);
            v1.y = fmaxf(acc[i][j][3] + b1, 0.f);
            if (ROUND_OUT) {
                v0.x = roundtf(v0.x); v0.y = roundtf(v0.y);
                v1.x = roundtf(v1.x); v1.y = roundtf(v1.y);
            }
            if (r0 < M) *(float2*)&C[(size_t)r0 * ldc + c] = v0;
            if (r1 < M) *(float2*)&C[(size_t)r1 * ldc + c] = v1;
        }
    }
}

// ---------------- pooling + head ----------------
__global__ __launch_bounds__(128) void pool_mean() {
    int g = blockIdx.x;
    int beg = g_gstart[g], end = g_gstart[g + 1];
    float4 acc = make_float4(0.f, 0.f, 0.f, 0.f);
    const int t = threadIdx.x;
    for (int n = beg; n < end; n++) {
        float4 v = ((const float4*)(g_h + (size_t)n * HID))[t];
        acc.x += v.x; acc.y += v.y; acc.z += v.z; acc.w += v.w;
    }
    float c = fmaxf((float)(end - beg), 1.f);
    acc.x = roundtf(acc.x / c); acc.y = roundtf(acc.y / c);
    acc.z = roundtf(acc.z / c); acc.w = roundtf(acc.w / c);
    ((float4*)(g_pool + (size_t)g * HID))[t] = acc;
}

__global__ void head2(const float* __restrict__ w, const float* __restrict__ b,
                      float* __restrict__ out) {
    int g = blockIdx.x;
    int o = threadIdx.x;
    if (o >= 12) return;
    float acc = b[o];
    const float* row = g_p1 + (size_t)g * 256;
#pragma unroll 8
    for (int k = 0; k < 256; k++) acc = fmaf(row[k], w[k * 12 + o], acc);
    out[(size_t)g * 12 + o] = acc;
}

// ---------------- launch ----------------
extern "C" void kernel_launch(void* const* d_in, const int* in_sizes, int n_in,
                              void* d_out, int out_size) {
    const float* x = (const float*)d_in[0];
    const int* ei = (const int*)d_in[1];
    const int* src = ei;
    const int* dst = ei + N_EDGES;
    const int* batch = (const int*)d_in[2];
    const float* c1w1 = (const float*)d_in[3];
    const float* c1b1 = (const float*)d_in[4];
    const float* c1w2 = (const float*)d_in[5];
    const float* c1b2 = (const float*)d_in[6];
    const float* c2w1 = (const float*)d_in[7];
    const float* c2b1 = (const float*)d_in[8];
    const float* c2w2 = (const float*)d_in[9];
    const float* c2b2 = (const float*)d_in[10];
    const float* c3w1 = (const float*)d_in[11];
    const float* c3b1 = (const float*)d_in[12];
    const float* c3w2 = (const float*)d_in[13];
    const float* c3b2 = (const float*)d_in[14];
    const float* lw1 = (const float*)d_in[15];
    const float* lb1 = (const float*)d_in[16];
    const float* lw2 = (const float*)d_in[17];
    const float* lb2 = (const float*)d_in[18];
    float* out = (float*)d_out;

    float *p_h, *p_t, *p_m, *p_pool, *p_p1, *p_wt;
    cudaGetSymbolAddress((void**)&p_h, g_h);
    cudaGetSymbolAddress((void**)&p_t, g_t);
    cudaGetSymbolAddress((void**)&p_m, g_m);
    cudaGetSymbolAddress((void**)&p_pool, g_pool);
    cudaGetSymbolAddress((void**)&p_p1, g_p1);
    cudaGetSymbolAddress((void**)&p_wt, g_wt);

    int* p_deg;
    cudaGetSymbolAddress((void**)&p_deg, g_deg);

    float* b_c1w2 = p_wt + 0 * 262144;
    float* b_c2w1 = p_wt + 1 * 262144;
    float* b_c2w2 = p_wt + 2 * 262144;
    float* b_c3w1 = p_wt + 3 * 262144;
    float* b_c3w2 = p_wt + 4 * 262144;
    float* t_lw1  = p_wt + 5 * 262144;  // plain [N,K] for head

    cudaFuncSetAttribute(gemm_pp<true>, cudaFuncAttributeMaxDynamicSharedMemorySize, GSM_BYTES);
    cudaFuncSetAttribute(gemm_pp<false>, cudaFuncAttributeMaxDynamicSharedMemorySize, GSM_BYTES);
    cudaFuncSetAttribute(gemm_ca<false>, cudaFuncAttributeMaxDynamicSharedMemorySize, GSM_BYTES);

    // ---- CSR build + graph ranges + weight prep ----
    cudaMemsetAsync(p_deg, 0, N_NODES * sizeof(int));
    deg_count<<<(N_EDGES + 255) / 256, 256>>>(dst);
    scan1<<<NCHUNK, 1024>>>();
    scan2<<<1, 32>>>();
    scan3<<<NCHUNK, 1024>>>();
    csr_scatter<<<(N_EDGES + 255) / 256, 256>>>(src, dst);
    graph_ranges<<<(N_GRAPHS + 256) / 256, 256>>>(batch);
    {
        const int WG = (512 * 512 + 255) / 256;
        w_to_bperm<<<WG, 256>>>(c1w2, b_c1w2, 512, 512);
        w_to_bperm<<<WG, 256>>>(c2w1, b_c2w1, 512, 512);
        w_to_bperm<<<WG, 256>>>(c2w2, b_c2w2, 512, 512);
        w_to_bperm<<<WG, 256>>>(c3w1, b_c3w1, 512, 512);
        w_to_bperm<<<WG, 256>>>(c3w2, b_c3w2, 512, 512);
        transposeKN<<<dim3(8, 16), dim3(32, 8)>>>(lw1, t_lw1, 512, 256);
    }

    const dim3 gg(4, M_PAD / 128);  // 782 m-blocks
    const dim3 hg(2, N_GRAPHS / 128);
    const dim3 agg_grid((N_NODES * 32 + 255) / 256, 4);
    const int KTN = 64;  // 512/8

    // ---- layer 1 ----
    csr_agg7<<<(N_NODES * 32 + 255) / 256, 256>>>(x);
    mlp_in7<<<2048, 256>>>(c1w1, c1b1);
    gemm_pp<false><<<gg, 256, GSM_BYTES>>>(N_NODES, KTN, HID, p_m, b_c1w2, c1b2, p_h);

    // ---- layer 2 ----
    csr_agg512_chunk<<<agg_grid, 256>>>();
    gemm_pp<true><<<gg, 256, GSM_BYTES>>>(N_NODES, KTN, HID, p_t, b_c2w1, c2b1, p_m);
    gemm_pp<false><<<gg, 256, GSM_BYTES>>>(N_NODES, KTN, HID, p_m, b_c2w2, c2b2, p_h);

    // ---- layer 3 ----
    csr_agg512_chunk<<<agg_grid, 256>>>();
    gemm_pp<true><<<gg, 256, GSM_BYTES>>>(N_NODES, KTN, HID, p_t, b_c3w1, c3b1, p_m);
    gemm_pp<false><<<gg, 256, GSM_BYTES>>>(N_NODES, KTN, HID, p_m, b_c3w2, c3b2, p_h);

    // ---- mean pool ----
    pool_mean<<<N_GRAPHS, 128>>>();

    // ---- head ----
    gemm_ca<false><<<hg, 256, GSM_BYTES>>>(N_GRAPHS, HID, 256, p_pool, t_lw1, lb1, p_p1);
    head2<<<N_GRAPHS, 32>>>(lw2, lb2, out);
}

// round 10
// speedup vs baseline: 1.4796x; 1.4796x over previous
#include <cuda_runtime.h>
#include <cuda_fp16.h>
#include <cstdint>
#include <cstddef>

#define N_NODES 100000
#define N_EDGES 1600000
#define N_GRAPHS 4096
#define HID 512
#define M_PAD 100096            // 782 * 128
#define NCHUNK ((N_NODES + 1023) / 1024)

// ---------------- scratch (device globals; allocation-free) ----------------
__device__ uint16_t g_hh[(size_t)M_PAD * HID];   // node features (half), padding rows stay 0
__device__ uint16_t g_th[(size_t)M_PAD * HID];   // agg output (half)
__device__ uint16_t g_mh[(size_t)M_PAD * HID];   // MLP hidden (half)
__device__ uint16_t g_poolh[(size_t)N_GRAPHS * HID];
__device__ float    g_h7[(size_t)N_NODES * 7];
__device__ float    g_p1[(size_t)N_GRAPHS * 256];
__device__ uint16_t g_wh[5 * 512 * 512 + 256 * 512];  // [N,K] half weights
// CSR scratch
__device__ int g_deg[N_NODES];
__device__ int g_rows[N_NODES + 1];
__device__ int g_cur[N_NODES];
__device__ int g_csr[N_EDGES];
__device__ int g_gstart[N_GRAPHS + 1];
__device__ int g_bsum[NCHUNK];
__device__ int g_boff[NCHUNK];

__device__ __forceinline__ uint16_t f2h(float x) {
    return __half_as_ushort(__float2half_rn(x));
}

// ---------------- CSR build ----------------
__global__ void deg_count(const int* __restrict__ dst) {
    int e = blockIdx.x * blockDim.x + threadIdx.x;
    if (e < N_EDGES) atomicAdd(&g_deg[dst[e]], 1);
}

__global__ __launch_bounds__(1024) void scan1() {
    __shared__ int s[1024];
    const int b = blockIdx.x;
    const int tid = threadIdx.x;
    const int i = b * 1024 + tid;
    int v = (i < N_NODES) ? g_deg[i] : 0;
    s[tid] = v;
    __syncthreads();
#pragma unroll
    for (int off = 1; off < 1024; off <<= 1) {
        int t = (tid >= off) ? s[tid - off] : 0;
        __syncthreads();
        s[tid] += t;
        __syncthreads();
    }
    if (i < N_NODES) g_rows[i] = s[tid] - v;
    if (tid == 1023) g_bsum[b] = s[1023];
}

__global__ void scan2() {
    if (threadIdx.x == 0) {
        int c = 0;
        for (int b = 0; b < NCHUNK; b++) { g_boff[b] = c; c += g_bsum[b]; }
        g_rows[N_NODES] = c;
    }
}

__global__ __launch_bounds__(1024) void scan3() {
    const int b = blockIdx.x;
    const int i = b * 1024 + threadIdx.x;
    if (i < N_NODES) {
        int r = g_rows[i] + g_boff[b];
        g_rows[i] = r;
        g_cur[i] = r;
    }
}

__global__ void csr_scatter(const int* __restrict__ src, const int* __restrict__ dst) {
    int e = blockIdx.x * blockDim.x + threadIdx.x;
    if (e >= N_EDGES) return;
    int pos = atomicAdd(&g_cur[dst[e]], 1);
    g_csr[pos] = src[e];
}

__global__ void graph_ranges(const int* __restrict__ batch) {
    int g = blockIdx.x * blockDim.x + threadIdx.x;
    if (g > N_GRAPHS) return;
    if (g == N_GRAPHS) { g_gstart[g] = N_NODES; return; }
    int lo = 0, hi = N_NODES;
    while (lo < hi) {
        int mid = (lo + hi) >> 1;
        if (batch[mid] < g) lo = mid + 1; else hi = mid;
    }
    g_gstart[g] = lo;
}

// ---------------- layer-1 aggregation (7 feats, exact fp32) ----------------
__global__ void csr_agg7(const float* __restrict__ x) {
    int w = (int)(((long long)blockIdx.x * blockDim.x + threadIdx.x) >> 5);
    int lane = threadIdx.x & 31;
    if (w >= N_NODES) return;
    int beg = g_rows[w], end = g_rows[w + 1];
    float a[7];
#pragma unroll
    for (int k = 0; k < 7; k++) a[k] = (lane == 0) ? x[(size_t)w * 7 + k] : 0.f;
    for (int e = beg + lane; e < end; e += 32) {
        int s = g_csr[e];
#pragma unroll
        for (int k = 0; k < 7; k++) a[k] += x[(size_t)s * 7 + k];
    }
#pragma unroll
    for (int off = 16; off; off >>= 1)
#pragma unroll
        for (int k = 0; k < 7; k++) a[k] += __shfl_xor_sync(0xFFFFFFFF, a[k], off);
    if (lane == 0) {
#pragma unroll
        for (int k = 0; k < 7; k++) g_h7[(size_t)w * 7 + k] = a[k];
    }
}

// g_mh = half(relu(g_h7 @ w1 + b1)) — exact fp32 math, half store
__global__ __launch_bounds__(256) void mlp_in7(const float* __restrict__ w,
                                               const float* __restrict__ bias) {
    __shared__ float sw[7][512];
    __shared__ float sb[512];
    for (int i = threadIdx.x; i < 7 * 512; i += 256) ((float*)sw)[i] = w[i];
    for (int i = threadIdx.x; i < 512; i += 256) sb[i] = bias[i];
    __syncthreads();
    for (int r = blockIdx.x; r < N_NODES; r += gridDim.x) {
        float h[7];
#pragma unroll
        for (int k = 0; k < 7; k++) h[k] = g_h7[(size_t)r * 7 + k];
#pragma unroll
        for (int jj = 0; jj < 2; jj++) {
            int j = threadIdx.x + jj * 256;
            float acc = sb[j];
#pragma unroll
            for (int k = 0; k < 7; k++) acc = fmaf(h[k], sw[k][j], acc);
            g_mh[(size_t)r * 512 + j] = f2h(fmaxf(acc, 0.f));
        }
    }
}

// ---------------- L2-blocked aggregation (half in/out, fp32 sums) ----------------
// blockIdx.y = column chunk (0..1), 256 halves (512B) each:
// working set per chunk = 100000*512B = 51 MB < L2.
__global__ __launch_bounds__(256) void csr_aggh_chunk() {
    int w = (int)(((long long)blockIdx.x * blockDim.x + threadIdx.x) >> 5);
    int lane = threadIdx.x & 31;
    if (w >= N_NODES) return;
    const int off = blockIdx.y * 256 + lane * 8;  // halves
    const int beg = g_rows[w], end = g_rows[w + 1];
    const uint16_t* base = g_hh + off;

    float acc[8];
    {
        uint4 s = *(const uint4*)(base + (size_t)w * HID);
        const __half2* p = (const __half2*)&s;
#pragma unroll
        for (int q = 0; q < 4; q++) {
            float2 f = __half22float2(p[q]);
            acc[q * 2] = f.x; acc[q * 2 + 1] = f.y;
        }
    }

    int e = beg;
    for (; e + 2 <= end; e += 2) {
        int s0 = g_csr[e], s1 = g_csr[e + 1];
        uint4 v0 = *(const uint4*)(base + (size_t)s0 * HID);
        uint4 v1 = *(const uint4*)(base + (size_t)s1 * HID);
        const __half2* p0 = (const __half2*)&v0;
        const __half2* p1 = (const __half2*)&v1;
#pragma unroll
        for (int q = 0; q < 4; q++) {
            float2 f0 = __half22float2(p0[q]);
            float2 f1 = __half22float2(p1[q]);
            acc[q * 2] += f0.x + f1.x;
            acc[q * 2 + 1] += f0.y + f1.y;
        }
    }
    if (e < end) {
        uint4 v0 = *(const uint4*)(base + (size_t)g_csr[e] * HID);
        const __half2* p0 = (const __half2*)&v0;
#pragma unroll
        for (int q = 0; q < 4; q++) {
            float2 f0 = __half22float2(p0[q]);
            acc[q * 2] += f0.x;
            acc[q * 2 + 1] += f0.y;
        }
    }

    uint4 o;
    __half2* po = (__half2*)&o;
#pragma unroll
    for (int q = 0; q < 4; q++)
        po[q] = __floats2half2_rn(acc[q * 2], acc[q * 2 + 1]);
    *(uint4*)(g_th + (size_t)w * HID + off) = o;
}

// weights [K,N] fp32 -> [N,K] half
__global__ void w_to_half(const float* __restrict__ in, uint16_t* __restrict__ outp,
                          int K, int N) {
    __shared__ float t[32][33];
    int n0 = blockIdx.x * 32, k0 = blockIdx.y * 32;
    int tx = threadIdx.x, ty = threadIdx.y;  // (32,8)
#pragma unroll
    for (int i = 0; i < 4; i++)
        t[ty + i * 8][tx] = in[(size_t)(k0 + ty + i * 8) * N + n0 + tx];
    __syncthreads();
#pragma unroll
    for (int i = 0; i < 4; i++)
        outp[(size_t)(n0 + ty + i * 8) * K + k0 + tx] = f2h(t[tx][ty + i * 8]);
}

// ---------------- FP16 mma GEMM, cp.async 3-stage, ldmatrix operands ----------------
// C[M,n-slice] = relu(A[M,512] @ B[n,512]^T + bias); A,B half row-major K=512.
// Tiles: BM=128, BN=128, BK=64 halves (128B rows). Stage = 32 KB, 3 stages = 96 KB.
// smem swizzle: 16B chunk index XOR (row & 7) -> ldmatrix conflict-free.

#define STGH_BYTES 32768
#define GHSM_BYTES (3 * STGH_BYTES)

__device__ __forceinline__ void cp16(uint32_t dst, const void* src) {
    asm volatile("cp.async.cg.shared.global [%0], [%1], 16;" :: "r"(dst), "l"(src));
}

__device__ __forceinline__ void ldsm4(uint32_t* r, uint32_t a) {
    asm volatile("ldmatrix.sync.aligned.m8n8.x4.shared.b16 {%0,%1,%2,%3}, [%4];"
                 : "=r"(r[0]), "=r"(r[1]), "=r"(r[2]), "=r"(r[3]) : "r"(a));
}
__device__ __forceinline__ void ldsm2(uint32_t* r, uint32_t a) {
    asm volatile("ldmatrix.sync.aligned.m8n8.x2.shared.b16 {%0,%1}, [%2];"
                 : "=r"(r[0]), "=r"(r[1]) : "r"(a));
}

__device__ __forceinline__ void mma_h(float* d, const uint32_t* a, const uint32_t* b) {
    asm volatile(
        "mma.sync.aligned.m16n8k16.row.col.f32.f16.f16.f32 "
        "{%0,%1,%2,%3},{%4,%5,%6,%7},{%8,%9},{%0,%1,%2,%3};\n"
        : "+f"(d[0]), "+f"(d[1]), "+f"(d[2]), "+f"(d[3])
        : "r"(a[0]), "r"(a[1]), "r"(a[2]), "r"(a[3]), "r"(b[0]), "r"(b[1]));
}

// OUT_F32: store float2 to C (fp32, ldc); else store half2 (uint32) to C (half, ldc).
template <bool OUT_F32>
__global__ __launch_bounds__(256) void gemm_h(
    int M, int ldc,
    const uint16_t* __restrict__ A, const uint16_t* __restrict__ B,
    const float* __restrict__ bias, void* __restrict__ Cv) {
    extern __shared__ __align__(128) char smc[];
    uint32_t smem_u32;
    asm("{ .reg .u64 t; cvta.to.shared.u64 t, %1; cvt.u32.u64 %0, t; }"
        : "=r"(smem_u32) : "l"(smc));

    const int tid = threadIdx.x;
    const int lane = tid & 31;
    const int warp = tid >> 5;
    const int wy = warp & 1;   // m 0/64
    const int wx = warp >> 1;  // n 0/32/64/96
    const int m0 = blockIdx.y * 128;
    const int n0 = blockIdx.x * 128;

    // cp.async mapping: 128 rows x 8 chunks(16B); thread -> row=tid>>1, 4 chunks
    const int cr = tid >> 1;
    const int cb = (tid & 1) * 4;

    auto issue = [&](int ks) {
        uint32_t sa = smem_u32 + (uint32_t)(ks % 3) * STGH_BYTES;
        uint32_t sb = sa + 16384;
        const uint16_t* Ar = A + (size_t)(m0 + cr) * 512 + ks * 64;
        const uint16_t* Br = B + (size_t)(n0 + cr) * 512 + ks * 64;
#pragma unroll
        for (int q = 0; q < 4; q++) {
            int ch = cb + q;
            int sch = ch ^ (cr & 7);
            cp16(sa + (uint32_t)(cr * 128 + sch * 16), Ar + ch * 8);
            cp16(sb + (uint32_t)(cr * 128 + sch * 16), Br + ch * 8);
        }
        asm volatile("cp.async.commit_group;");
    };

    issue(0);
    issue(1);

    float acc[4][4][4];
#pragma unroll
    for (int i = 0; i < 4; i++)
#pragma unroll
        for (int j = 0; j < 4; j++)
#pragma unroll
            for (int r = 0; r < 4; r++) acc[i][j][r] = 0.f;

    // ldmatrix per-lane row/ksel
    const int arow = lane & 15;         // A: rows 0..15 of tile
    const int asel = lane >> 4;         // A: k half (0/1)
    const int brow = lane & 7;          // B: rows 0..7 of tile
    const int bsel = (lane >> 3) & 1;   // B: k half (0/1), lanes 0..15 used

    const int nks = 8;  // 512/64
    for (int ks = 0; ks < nks; ks++) {
        if (ks + 2 < nks) issue(ks + 2);
        else asm volatile("cp.async.commit_group;");
        asm volatile("cp.async.wait_group %0;" :: "n"(2));
        __syncthreads();

        uint32_t sa = smem_u32 + (uint32_t)(ks % 3) * STGH_BYTES;
        uint32_t sb = sa + 16384;
#pragma unroll
        for (int kk = 0; kk < 4; kk++) {
            uint32_t af[4][4], bf[4][2];
            const int ach = (2 * kk + asel) ^ (arow & 7);
            const int bch = (2 * kk + bsel) ^ brow;
#pragma unroll
            for (int i = 0; i < 4; i++)
                ldsm4(af[i], sa + (uint32_t)((wy * 64 + i * 16 + arow) * 128 + ach * 16));
#pragma unroll
            for (int j = 0; j < 4; j++)
                ldsm2(bf[j], sb + (uint32_t)((wx * 32 + j * 8 + brow) * 128 + bch * 16));
#pragma unroll
            for (int i = 0; i < 4; i++)
#pragma unroll
                for (int j = 0; j < 4; j++) mma_h(acc[i][j], af[i], bf[j]);
        }
        __syncthreads();
    }

    const int crow = lane >> 2;
    const int ccol = (lane & 3) << 1;
#pragma unroll
    for (int i = 0; i < 4; i++) {
        int r0 = m0 + wy * 64 + i * 16 + crow;
        int r1 = r0 + 8;
#pragma unroll
        for (int j = 0; j < 4; j++) {
            int c = n0 + wx * 32 + j * 8 + ccol;
            float b0 = bias[c], b1 = bias[c + 1];
            float v00 = fmaxf(acc[i][j][0] + b0, 0.f);
            float v01 = fmaxf(acc[i][j][1] + b1, 0.f);
            float v10 = fmaxf(acc[i][j][2] + b0, 0.f);
            float v11 = fmaxf(acc[i][j][3] + b1, 0.f);
            if (OUT_F32) {
                float* C = (float*)Cv;
                if (r0 < M) { float2 v = {v00, v01}; *(float2*)&C[(size_t)r0 * ldc + c] = v; }
                if (r1 < M) { float2 v = {v10, v11}; *(float2*)&C[(size_t)r1 * ldc + c] = v; }
            } else {
                uint16_t* C = (uint16_t*)Cv;
                if (r0 < M) {
                    __half2 v = __floats2half2_rn(v00, v01);
                    *(uint32_t*)&C[(size_t)r0 * ldc + c] = *(uint32_t*)&v;
                }
                if (r1 < M) {
                    __half2 v = __floats2half2_rn(v10, v11);
                    *(uint32_t*)&C[(size_t)r1 * ldc + c] = *(uint32_t*)&v;
                }
            }
        }
    }
}

// ---------------- pooling + head ----------------
__global__ __launch_bounds__(128) void pool_mean() {
    int g = blockIdx.x;
    int beg = g_gstart[g], end = g_gstart[g + 1];
    const int t = threadIdx.x;  // 4 halves each
    float a0 = 0.f, a1 = 0.f, a2 = 0.f, a3 = 0.f;
    for (int n = beg; n < end; n++) {
        uint2 v = *(const uint2*)(g_hh + (size_t)n * HID + t * 4);
        float2 f0 = __half22float2(*(__half2*)&v.x);
        float2 f1 = __half22float2(*(__half2*)&v.y);
        a0 += f0.x; a1 += f0.y; a2 += f1.x; a3 += f1.y;
    }
    float c = fmaxf((float)(end - beg), 1.f);
    uint2 o;
    __half2 o0 = __floats2half2_rn(a0 / c, a1 / c);
    __half2 o1 = __floats2half2_rn(a2 / c, a3 / c);
    o.x = *(uint32_t*)&o0; o.y = *(uint32_t*)&o1;
    *(uint2*)(g_poolh + (size_t)g * HID + t * 4) = o;
}

__global__ void head2(const float* __restrict__ w, const float* __restrict__ b,
                      float* __restrict__ out) {
    int g = blockIdx.x;
    int o = threadIdx.x;
    if (o >= 12) return;
    float acc = b[o];
    const float* row = g_p1 + (size_t)g * 256;
#pragma unroll 8
    for (int k = 0; k < 256; k++) acc = fmaf(row[k], w[k * 12 + o], acc);
    out[(size_t)g * 12 + o] = acc;
}

// ---------------- launch ----------------
extern "C" void kernel_launch(void* const* d_in, const int* in_sizes, int n_in,
                              void* d_out, int out_size) {
    const float* x = (const float*)d_in[0];
    const int* ei = (const int*)d_in[1];
    const int* src = ei;
    const int* dst = ei + N_EDGES;
    const int* batch = (const int*)d_in[2];
    const float* c1w1 = (const float*)d_in[3];
    const float* c1b1 = (const float*)d_in[4];
    const float* c1w2 = (const float*)d_in[5];
    const float* c1b2 = (const float*)d_in[6];
    const float* c2w1 = (const float*)d_in[7];
    const float* c2b1 = (const float*)d_in[8];
    const float* c2w2 = (const float*)d_in[9];
    const float* c2b2 = (const float*)d_in[10];
    const float* c3w1 = (const float*)d_in[11];
    const float* c3b1 = (const float*)d_in[12];
    const float* c3w2 = (const float*)d_in[13];
    const float* c3b2 = (const float*)d_in[14];
    const float* lw1 = (const float*)d_in[15];
    const float* lb1 = (const float*)d_in[16];
    const float* lw2 = (const float*)d_in[17];
    const float* lb2 = (const float*)d_in[18];
    float* out = (float*)d_out;

    uint16_t *p_hh, *p_th, *p_mh, *p_poolh, *p_wh;
    float *p_p1;
    int *p_deg;
    cudaGetSymbolAddress((void**)&p_hh, g_hh);
    cudaGetSymbolAddress((void**)&p_th, g_th);
    cudaGetSymbolAddress((void**)&p_mh, g_mh);
    cudaGetSymbolAddress((void**)&p_poolh, g_poolh);
    cudaGetSymbolAddress((void**)&p_wh, g_wh);
    cudaGetSymbolAddress((void**)&p_p1, g_p1);
    cudaGetSymbolAddress((void**)&p_deg, g_deg);

    uint16_t* h_c1w2 = p_wh + 0 * 262144;
    uint16_t* h_c2w1 = p_wh + 1 * 262144;
    uint16_t* h_c2w2 = p_wh + 2 * 262144;
    uint16_t* h_c3w1 = p_wh + 3 * 262144;
    uint16_t* h_c3w2 = p_wh + 4 * 262144;
    uint16_t* h_lw1  = p_wh + 5 * 262144;

    cudaFuncSetAttribute(gemm_h<true>, cudaFuncAttributeMaxDynamicSharedMemorySize, GHSM_BYTES);
    cudaFuncSetAttribute(gemm_h<false>, cudaFuncAttributeMaxDynamicSharedMemorySize, GHSM_BYTES);

    // ---- CSR build + graph ranges + weight prep ----
    cudaMemsetAsync(p_deg, 0, N_NODES * sizeof(int));
    deg_count<<<(N_EDGES + 255) / 256, 256>>>(dst);
    scan1<<<NCHUNK, 1024>>>();
    scan2<<<1, 32>>>();
    scan3<<<NCHUNK, 1024>>>();
    csr_scatter<<<(N_EDGES + 255) / 256, 256>>>(src, dst);
    graph_ranges<<<(N_GRAPHS + 256) / 256, 256>>>(batch);
    {
        dim3 b(32, 8);
        w_to_half<<<dim3(16, 16), b>>>(c1w2, h_c1w2, 512, 512);
        w_to_half<<<dim3(16, 16), b>>>(c2w1, h_c2w1, 512, 512);
        w_to_half<<<dim3(16, 16), b>>>(c2w2, h_c2w2, 512, 512);
        w_to_half<<<dim3(16, 16), b>>>(c3w1, h_c3w1, 512, 512);
        w_to_half<<<dim3(16, 16), b>>>(c3w2, h_c3w2, 512, 512);
        w_to_half<<<dim3(8, 16), b>>>(lw1, h_lw1, 512, 256);
    }

    const dim3 gg(4, M_PAD / 128);           // 512-wide GEMMs
    const dim3 hg(2, N_GRAPHS / 128);        // head: N=256, M=4096
    const dim3 agg_grid((N_NODES * 32 + 255) / 256, 2);

    // ---- layer 1 ----
    csr_agg7<<<(N_NODES * 32 + 255) / 256, 256>>>(x);
    mlp_in7<<<2048, 256>>>(c1w1, c1b1);
    gemm_h<false><<<gg, 256, GHSM_BYTES>>>(N_NODES, HID, p_mh, h_c1w2, c1b2, p_hh);

    // ---- layer 2 ----
    csr_aggh_chunk<<<agg_grid, 256>>>();
    gemm_h<false><<<gg, 256, GHSM_BYTES>>>(N_NODES, HID, p_th, h_c2w1, c2b1, p_mh);
    gemm_h<false><<<gg, 256, GHSM_BYTES>>>(N_NODES, HID, p_mh, h_c2w2, c2b2, p_hh);

    // ---- layer 3 ----
    csr_aggh_chunk<<<agg_grid, 256>>>();
    gemm_h<false><<<gg, 256, GHSM_BYTES>>>(N_NODES, HID, p_th, h_c3w1, c3b1, p_mh);
    gemm_h<false><<<gg, 256, GHSM_BYTES>>>(N_NODES, HID, p_mh, h_c3w2, c3b2, p_hh);

    // ---- mean pool ----
    pool_mean<<<N_GRAPHS, 128>>>();

    // ---- head ----
    gemm_h<true><<<hg, 256, GHSM_BYTES>>>(N_GRAPHS, 256, p_poolh, h_lw1, lb1, p_p1);
    head2<<<N_GRAPHS, 32>>>(lw2, lb2, out);
}

// round 12
// speedup vs baseline: 1.5333x; 1.0363x over previous
#include <cuda_runtime.h>
#include <cuda_fp16.h>
#include <cstdint>
#include <cstddef>

#define N_NODES 100000
#define N_EDGES 1600000
#define N_GRAPHS 4096
#define HID 512
#define M_PAD 100096            // 782 * 128
#define NCHUNK ((N_NODES + 1023) / 1024)

// ---------------- scratch (device globals; allocation-free) ----------------
__device__ uint16_t g_hh[(size_t)M_PAD * HID];   // node features (half)
__device__ uint16_t g_th[(size_t)M_PAD * HID];   // agg output (half)
__device__ uint16_t g_mh[(size_t)M_PAD * HID];   // MLP hidden (half)
__device__ uint16_t g_poolh[(size_t)N_GRAPHS * HID];
__device__ float    g_h7[(size_t)N_NODES * 7];
__device__ float    g_p1[(size_t)N_GRAPHS * 256];
__device__ uint16_t g_wh[5 * 512 * 512 + 256 * 512];  // [N,K] half weights
// CSR scratch
__device__ int g_deg[N_NODES];
__device__ int g_rows[N_NODES + 1];
__device__ int g_cur[N_NODES];
__device__ int g_csr[N_EDGES];
__device__ int g_gstart[N_GRAPHS + 1];
__device__ int g_bsum[NCHUNK];
__device__ int g_boff[NCHUNK];

__device__ __forceinline__ uint16_t f2h(float x) {
    return __half_as_ushort(__float2half_rn(x));
}

// ---------------- CSR build ----------------
__global__ void deg_count(const int* __restrict__ dst) {
    int e = blockIdx.x * blockDim.x + threadIdx.x;
    if (e < N_EDGES) atomicAdd(&g_deg[dst[e]], 1);
}

__global__ __launch_bounds__(1024) void scan1() {
    __shared__ int s[1024];
    const int b = blockIdx.x;
    const int tid = threadIdx.x;
    const int i = b * 1024 + tid;
    int v = (i < N_NODES) ? g_deg[i] : 0;
    s[tid] = v;
    __syncthreads();
#pragma unroll
    for (int off = 1; off < 1024; off <<= 1) {
        int t = (tid >= off) ? s[tid - off] : 0;
        __syncthreads();
        s[tid] += t;
        __syncthreads();
    }
    if (i < N_NODES) g_rows[i] = s[tid] - v;
    if (tid == 1023) g_bsum[b] = s[1023];
}

__global__ void scan2() {
    if (threadIdx.x == 0) {
        int c = 0;
        for (int b = 0; b < NCHUNK; b++) { g_boff[b] = c; c += g_bsum[b]; }
        g_rows[N_NODES] = c;
    }
}

__global__ __launch_bounds__(1024) void scan3() {
    const int b = blockIdx.x;
    const int i = b * 1024 + threadIdx.x;
    if (i < N_NODES) {
        int r = g_rows[i] + g_boff[b];
        g_rows[i] = r;
        g_cur[i] = r;
    }
}

__global__ void csr_scatter(const int* __restrict__ src, const int* __restrict__ dst) {
    int e = blockIdx.x * blockDim.x + threadIdx.x;
    if (e >= N_EDGES) return;
    int pos = atomicAdd(&g_cur[dst[e]], 1);
    g_csr[pos] = src[e];
}

__global__ void graph_ranges(const int* __restrict__ batch) {
    int g = blockIdx.x * blockDim.x + threadIdx.x;
    if (g > N_GRAPHS) return;
    if (g == N_GRAPHS) { g_gstart[g] = N_NODES; return; }
    int lo = 0, hi = N_NODES;
    while (lo < hi) {
        int mid = (lo + hi) >> 1;
        if (batch[mid] < g) lo = mid + 1; else hi = mid;
    }
    g_gstart[g] = lo;
}

// ---------------- layer-1 aggregation (7 feats, exact fp32) ----------------
__global__ void csr_agg7(const float* __restrict__ x) {
    int w = (int)(((long long)blockIdx.x * blockDim.x + threadIdx.x) >> 5);
    int lane = threadIdx.x & 31;
    if (w >= N_NODES) return;
    int beg = g_rows[w], end = g_rows[w + 1];
    float a[7];
#pragma unroll
    for (int k = 0; k < 7; k++) a[k] = (lane == 0) ? x[(size_t)w * 7 + k] : 0.f;
    for (int e = beg + lane; e < end; e += 32) {
        int s = g_csr[e];
#pragma unroll
        for (int k = 0; k < 7; k++) a[k] += x[(size_t)s * 7 + k];
    }
#pragma unroll
    for (int off = 16; off; off >>= 1)
#pragma unroll
        for (int k = 0; k < 7; k++) a[k] += __shfl_xor_sync(0xFFFFFFFF, a[k], off);
    if (lane == 0) {
#pragma unroll
        for (int k = 0; k < 7; k++) g_h7[(size_t)w * 7 + k] = a[k];
    }
}

// g_mh = half(relu(g_h7 @ w1 + b1)) — exact fp32 math, half store
__global__ __launch_bounds__(256) void mlp_in7(const float* __restrict__ w,
                                               const float* __restrict__ bias) {
    __shared__ float sw[7][512];
    __shared__ float sb[512];
    for (int i = threadIdx.x; i < 7 * 512; i += 256) ((float*)sw)[i] = w[i];
    for (int i = threadIdx.x; i < 512; i += 256) sb[i] = bias[i];
    __syncthreads();
    for (int r = blockIdx.x; r < N_NODES; r += gridDim.x) {
        float h[7];
#pragma unroll
        for (int k = 0; k < 7; k++) h[k] = g_h7[(size_t)r * 7 + k];
#pragma unroll
        for (int jj = 0; jj < 2; jj++) {
            int j = threadIdx.x + jj * 256;
            float acc = sb[j];
#pragma unroll
            for (int k = 0; k < 7; k++) acc = fmaf(h[k], sw[k][j], acc);
            g_mh[(size_t)r * 512 + j] = f2h(fmaxf(acc, 0.f));
        }
    }
}

// ---------------- L2-blocked aggregation (half in/out, fp32 sums) ----------------
__global__ __launch_bounds__(256) void csr_aggh_chunk() {
    int w = (int)(((long long)blockIdx.x * blockDim.x + threadIdx.x) >> 5);
    int lane = threadIdx.x & 31;
    if (w >= N_NODES) return;
    const int off = blockIdx.y * 256 + lane * 8;  // halves
    const int beg = g_rows[w], end = g_rows[w + 1];
    const uint16_t* base = g_hh + off;

    float acc[8];
    {
        uint4 s = *(const uint4*)(base + (size_t)w * HID);
        const __half2* p = (const __half2*)&s;
#pragma unroll
        for (int q = 0; q < 4; q++) {
            float2 f = __half22float2(p[q]);
            acc[q * 2] = f.x; acc[q * 2 + 1] = f.y;
        }
    }

    int e = beg;
    for (; e + 4 <= end; e += 4) {
        int s0 = g_csr[e], s1 = g_csr[e + 1], s2 = g_csr[e + 2], s3 = g_csr[e + 3];
        uint4 v0 = *(const uint4*)(base + (size_t)s0 * HID);
        uint4 v1 = *(const uint4*)(base + (size_t)s1 * HID);
        uint4 v2 = *(const uint4*)(base + (size_t)s2 * HID);
        uint4 v3 = *(const uint4*)(base + (size_t)s3 * HID);
        const __half2* p0 = (const __half2*)&v0;
        const __half2* p1 = (const __half2*)&v1;
        const __half2* p2 = (const __half2*)&v2;
        const __half2* p3 = (const __half2*)&v3;
#pragma unroll
        for (int q = 0; q < 4; q++) {
            float2 f0 = __half22float2(p0[q]);
            float2 f1 = __half22float2(p1[q]);
            float2 f2 = __half22float2(p2[q]);
            float2 f3 = __half22float2(p3[q]);
            acc[q * 2]     += (f0.x + f1.x) + (f2.x + f3.x);
            acc[q * 2 + 1] += (f0.y + f1.y) + (f2.y + f3.y);
        }
    }
    for (; e < end; e++) {
        uint4 v0 = *(const uint4*)(base + (size_t)g_csr[e] * HID);
        const __half2* p0 = (const __half2*)&v0;
#pragma unroll
        for (int q = 0; q < 4; q++) {
            float2 f0 = __half22float2(p0[q]);
            acc[q * 2] += f0.x;
            acc[q * 2 + 1] += f0.y;
        }
    }

    uint4 o;
    __half2* po = (__half2*)&o;
#pragma unroll
    for (int q = 0; q < 4; q++)
        po[q] = __floats2half2_rn(acc[q * 2], acc[q * 2 + 1]);
    *(uint4*)(g_th + (size_t)w * HID + off) = o;
}

// weights [K,N] fp32 -> [N,K] half
__global__ void w_to_half(const float* __restrict__ in, uint16_t* __restrict__ outp,
                          int K, int N) {
    __shared__ float t[32][33];
    int n0 = blockIdx.x * 32, k0 = blockIdx.y * 32;
    int tx = threadIdx.x, ty = threadIdx.y;  // (32,8)
#pragma unroll
    for (int i = 0; i < 4; i++)
        t[ty + i * 8][tx] = in[(size_t)(k0 + ty + i * 8) * N + n0 + tx];
    __syncthreads();
#pragma unroll
    for (int i = 0; i < 4; i++)
        outp[(size_t)(n0 + ty + i * 8) * K + k0 + tx] = f2h(t[tx][ty + i * 8]);
}

// ---------------- FP16 mma GEMM, 2-stage cp.async, 2 CTAs/SM ----------------
// Tiles: BM=128, BN=128, BK=64 halves (128B rows). Stage = 32 KB, 2 stages = 64 KB.
#define STGH_BYTES 32768
#define GHSM_BYTES (2 * STGH_BYTES)

__device__ __forceinline__ void cp16(uint32_t dst, const void* src) {
    asm volatile("cp.async.cg.shared.global [%0], [%1], 16;" :: "r"(dst), "l"(src));
}

__device__ __forceinline__ void ldsm4(uint32_t* r, uint32_t a) {
    asm volatile("ldmatrix.sync.aligned.m8n8.x4.shared.b16 {%0,%1,%2,%3}, [%4];"
                 : "=r"(r[0]), "=r"(r[1]), "=r"(r[2]), "=r"(r[3]) : "r"(a));
}
__device__ __forceinline__ void ldsm2(uint32_t* r, uint32_t a) {
    asm volatile("ldmatrix.sync.aligned.m8n8.x2.shared.b16 {%0,%1}, [%2];"
                 : "=r"(r[0]), "=r"(r[1]) : "r"(a));
}

__device__ __forceinline__ void mma_h(float* d, const uint32_t* a, const uint32_t* b) {
    asm volatile(
        "mma.sync.aligned.m16n8k16.row.col.f32.f16.f16.f32 "
        "{%0,%1,%2,%3},{%4,%5,%6,%7},{%8,%9},{%0,%1,%2,%3};\n"
        : "+f"(d[0]), "+f"(d[1]), "+f"(d[2]), "+f"(d[3])
        : "r"(a[0]), "r"(a[1]), "r"(a[2]), "r"(a[3]), "r"(b[0]), "r"(b[1]));
}

// OUT_F32: store float2 to C (fp32, ldc); else half2 to C (half, ldc).
template <bool OUT_F32>
__global__ __launch_bounds__(256, 2) void gemm_h(
    int M, int ldc,
    const uint16_t* __restrict__ A, const uint16_t* __restrict__ B,
    const float* __restrict__ bias, void* __restrict__ Cv) {
    extern __shared__ __align__(128) char smc[];
    uint32_t smem_u32;
    asm("{ .reg .u64 t; cvta.to.shared.u64 t, %1; cvt.u32.u64 %0, t; }"
        : "=r"(smem_u32) : "l"(smc));

    const int tid = threadIdx.x;
    const int lane = tid & 31;
    const int warp = tid >> 5;
    const int wy = warp & 1;   // m 0/64
    const int wx = warp >> 1;  // n 0/32/64/96
    const int m0 = blockIdx.y * 128;
    const int n0 = blockIdx.x * 128;

    const int cr = tid >> 1;
    const int cb = (tid & 1) * 4;

    auto issue = [&](int ks) {
        uint32_t sa = smem_u32 + (uint32_t)(ks & 1) * STGH_BYTES;
        uint32_t sb = sa + 16384;
        const uint16_t* Ar = A + (size_t)(m0 + cr) * 512 + ks * 64;
        const uint16_t* Br = B + (size_t)(n0 + cr) * 512 + ks * 64;
#pragma unroll
        for (int q = 0; q < 4; q++) {
            int ch = cb + q;
            int sch = ch ^ (cr & 7);
            cp16(sa + (uint32_t)(cr * 128 + sch * 16), Ar + ch * 8);
            cp16(sb + (uint32_t)(cr * 128 + sch * 16), Br + ch * 8);
        }
        asm volatile("cp.async.commit_group;");
    };

    issue(0);

    float acc[4][4][4];
#pragma unroll
    for (int i = 0; i < 4; i++)
#pragma unroll
        for (int j = 0; j < 4; j++)
#pragma unroll
            for (int r = 0; r < 4; r++) acc[i][j][r] = 0.f;

    const int arow = lane & 15;
    const int asel = lane >> 4;
    const int brow = lane & 7;
    const int bsel = (lane >> 3) & 1;

    const int nks = 8;  // 512/64
    for (int ks = 0; ks < nks; ks++) {
        if (ks + 1 < nks) issue(ks + 1);
        else asm volatile("cp.async.commit_group;");
        asm volatile("cp.async.wait_group %0;" :: "n"(1));
        __syncthreads();

        uint32_t sa = smem_u32 + (uint32_t)(ks & 1) * STGH_BYTES;
        uint32_t sb = sa + 16384;
#pragma unroll
        for (int kk = 0; kk < 4; kk++) {
            uint32_t af[4][4], bf[4][2];
            const int ach = (2 * kk + asel) ^ (arow & 7);
            const int bch = (2 * kk + bsel) ^ brow;
#pragma unroll
            for (int i = 0; i < 4; i++)
                ldsm4(af[i], sa + (uint32_t)((wy * 64 + i * 16 + arow) * 128 + ach * 16));
#pragma unroll
            for (int j = 0; j < 4; j++)
                ldsm2(bf[j], sb + (uint32_t)((wx * 32 + j * 8 + brow) * 128 + bch * 16));
#pragma unroll
            for (int i = 0; i < 4; i++)
#pragma unroll
                for (int j = 0; j < 4; j++) mma_h(acc[i][j], af[i], bf[j]);
        }
        __syncthreads();
    }

    const int crow = lane >> 2;
    const int ccol = (lane & 3) << 1;
#pragma unroll
    for (int i = 0; i < 4; i++) {
        int r0 = m0 + wy * 64 + i * 16 + crow;
        int r1 = r0 + 8;
#pragma unroll
        for (int j = 0; j < 4; j++) {
            int c = n0 + wx * 32 + j * 8 + ccol;
            float b0 = bias[c], b1 = bias[c + 1];
            float v00 = fmaxf(acc[i][j][0] + b0, 0.f);
            float v01 = fmaxf(acc[i][j][1] + b1, 0.f);
            float v10 = fmaxf(acc[i][j][2] + b0, 0.f);
            float v11 = fmaxf(acc[i][j][3] + b1, 0.f);
            if (OUT_F32) {
                float* C = (float*)Cv;
                if (r0 < M) { float2 v = {v00, v01}; *(float2*)&C[(size_t)r0 * ldc + c] = v; }
                if (r1 < M) { float2 v = {v10, v11}; *(float2*)&C[(size_t)r1 * ldc + c] = v; }
            } else {
                uint16_t* C = (uint16_t*)Cv;
                if (r0 < M) {
                    __half2 v = __floats2half2_rn(v00, v01);
                    *(uint32_t*)&C[(size_t)r0 * ldc + c] = *(uint32_t*)&v;
                }
                if (r1 < M) {
                    __half2 v = __floats2half2_rn(v10, v11);
                    *(uint32_t*)&C[(size_t)r1 * ldc + c] = *(uint32_t*)&v;
                }
            }
        }
    }
}

// ---------------- pooling + head ----------------
__global__ __launch_bounds__(128) void pool_mean() {
    int g = blockIdx.x;
    int beg = g_gstart[g], end = g_gstart[g + 1];
    const int t = threadIdx.x;  // 4 halves each
    float a0 = 0.f, a1 = 0.f, a2 = 0.f, a3 = 0.f;
    for (int n = beg; n < end; n++) {
        uint2 v = *(const uint2*)(g_hh + (size_t)n * HID + t * 4);
        float2 f0 = __half22float2(*(__half2*)&v.x);
        float2 f1 = __half22float2(*(__half2*)&v.y);
        a0 += f0.x; a1 += f0.y; a2 += f1.x; a3 += f1.y;
    }
    float c = fmaxf((float)(end - beg), 1.f);
    uint2 o;
    __half2 o0 = __floats2half2_rn(a0 / c, a1 / c);
    __half2 o1 = __floats2half2_rn(a2 / c, a3 / c);
    o.x = *(uint32_t*)&o0; o.y = *(uint32_t*)&o1;
    *(uint2*)(g_poolh + (size_t)g * HID + t * 4) = o;
}

__global__ void head2(const float* __restrict__ w, const float* __restrict__ b,
                      float* __restrict__ out) {
    int g = blockIdx.x;
    int o = threadIdx.x;
    if (o >= 12) return;
    float acc = b[o];
    const float* row = g_p1 + (size_t)g * 256;
#pragma unroll 8
    for (int k = 0; k < 256; k++) acc = fmaf(row[k], w[k * 12 + o], acc);
    out[(size_t)g * 12 + o] = acc;
}

// ---------------- launch ----------------
extern "C" void kernel_launch(void* const* d_in, const int* in_sizes, int n_in,
                              void* d_out, int out_size) {
    const float* x = (const float*)d_in[0];
    const int* ei = (const int*)d_in[1];
    const int* src = ei;
    const int* dst = ei + N_EDGES;
    const int* batch = (const int*)d_in[2];
    const float* c1w1 = (const float*)d_in[3];
    const float* c1b1 = (const float*)d_in[4];
    const float* c1w2 = (const float*)d_in[5];
    const float* c1b2 = (const float*)d_in[6];
    const float* c2w1 = (const float*)d_in[7];
    const float* c2b1 = (const float*)d_in[8];
    const float* c2w2 = (const float*)d_in[9];
    const float* c2b2 = (const float*)d_in[10];
    const float* c3w1 = (const float*)d_in[11];
    const float* c3b1 = (const float*)d_in[12];
    const float* c3w2 = (const float*)d_in[13];
    const float* c3b2 = (const float*)d_in[14];
    const float* lw1 = (const float*)d_in[15];
    const float* lb1 = (const float*)d_in[16];
    const float* lw2 = (const float*)d_in[17];
    const float* lb2 = (const float*)d_in[18];
    float* out = (float*)d_out;

    uint16_t *p_hh, *p_th, *p_mh, *p_poolh, *p_wh;
    float *p_p1;
    int *p_deg;
    cudaGetSymbolAddress((void**)&p_hh, g_hh);
    cudaGetSymbolAddress((void**)&p_th, g_th);
    cudaGetSymbolAddress((void**)&p_mh, g_mh);
    cudaGetSymbolAddress((void**)&p_poolh, g_poolh);
    cudaGetSymbolAddress((void**)&p_wh, g_wh);
    cudaGetSymbolAddress((void**)&p_p1, g_p1);
    cudaGetSymbolAddress((void**)&p_deg, g_deg);

    uint16_t* h_c1w2 = p_wh + 0 * 262144;
    uint16_t* h_c2w1 = p_wh + 1 * 262144;
    uint16_t* h_c2w2 = p_wh + 2 * 262144;
    uint16_t* h_c3w1 = p_wh + 3 * 262144;
    uint16_t* h_c3w2 = p_wh + 4 * 262144;
    uint16_t* h_lw1  = p_wh + 5 * 262144;

    cudaFuncSetAttribute(gemm_h<true>, cudaFuncAttributeMaxDynamicSharedMemorySize, GHSM_BYTES);
    cudaFuncSetAttribute(gemm_h<false>, cudaFuncAttributeMaxDynamicSharedMemorySize, GHSM_BYTES);

    // ---- CSR build + graph ranges + weight prep ----
    cudaMemsetAsync(p_deg, 0, N_NODES * sizeof(int));
    deg_count<<<(N_EDGES + 255) / 256, 256>>>(dst);
    scan1<<<NCHUNK, 1024>>>();
    scan2<<<1, 32>>>();
    scan3<<<NCHUNK, 1024>>>();
    csr_scatter<<<(N_EDGES + 255) / 256, 256>>>(src, dst);
    graph_ranges<<<(N_GRAPHS + 256) / 256, 256>>>(batch);
    {
        dim3 b(32, 8);
        w_to_half<<<dim3(16, 16), b>>>(c1w2, h_c1w2, 512, 512);
        w_to_half<<<dim3(16, 16), b>>>(c2w1, h_c2w1, 512, 512);
        w_to_half<<<dim3(16, 16), b>>>(c2w2, h_c2w2, 512, 512);
        w_to_half<<<dim3(16, 16), b>>>(c3w1, h_c3w1, 512, 512);
        w_to_half<<<dim3(16, 16), b>>>(c3w2, h_c3w2, 512, 512);
        w_to_half<<<dim3(8, 16), b>>>(lw1, h_lw1, 512, 256);
    }

    const dim3 gg(4, M_PAD / 128);
    const dim3 hg(2, N_GRAPHS / 128);
    const dim3 agg_grid((N_NODES * 32 + 255) / 256, 2);

    // ---- layer 1 ----
    csr_agg7<<<(N_NODES * 32 + 255) / 256, 256>>>(x);
    mlp_in7<<<2048, 256>>>(c1w1, c1b1);
    gemm_h<false><<<gg, 256, GHSM_BYTES>>>(N_NODES, HID, p_mh, h_c1w2, c1b2, p_hh);

    // ---- layer 2 ----
    csr_aggh_chunk<<<agg_grid, 256>>>();
    gemm_h<false><<<gg, 256, GHSM_BYTES>>>(N_NODES, HID, p_th, h_c2w1, c2b1, p_mh);
    gemm_h<false><<<gg, 256, GHSM_BYTES>>>(N_NODES, HID, p_mh, h_c2w2, c2b2, p_hh);

    // ---- layer 3 ----
    csr_aggh_chunk<<<agg_grid, 256>>>();
    gemm_h<false><<<gg, 256, GHSM_BYTES>>>(N_NODES, HID, p_th, h_c3w1, c3b1, p_mh);
    gemm_h<false><<<gg, 256, GHSM_BYTES>>>(N_NODES, HID, p_mh, h_c3w2, c3b2, p_hh);

    // ---- mean pool ----
    pool_mean<<<N_GRAPHS, 128>>>();

    // ---- head ----
    gemm_h<true><<<hg, 256, GHSM_BYTES>>>(N_GRAPHS, 256, p_poolh, h_lw1, lb1, p_p1);
    head2<<<N_GRAPHS, 32>>>(lw2, lb2, out);
}